// round 9
// baseline (speedup 1.0000x reference)
#include <cuda_runtime.h>

// ============================================================================
// FrFDConv: weights = polar(FrFT2D(spec)) . polar_w  ;  out = conv3x3(x, weights)
// R4: fp32 direct conv with packed fma.rn.f32x2.
//   - weights pre-duplicated as {w,w} 64-bit pairs at generation time
//     (removes 144 ALU MOVs per ci-iteration -> alu pipe ~45% -> <10%)
//   - staging offsets hoisted out of the ci loop (no more idx/34 per ci)
//   - double-buffered input patch, register prefetch, 1 barrier per ci
// ============================================================================

#define PI_F 3.14159265358979323846f

typedef unsigned long long ull;

// Duplicated-pair weights: g_w2[(co*64+ci)*9 + t] = {w, w}
__device__ ull g_w2[64 * 64 * 9];

// ------------------------------ complex helpers -----------------------------
struct c2f { float re, im; };

__device__ __forceinline__ c2f cmul(c2f a, c2f b) {
    return { a.re * b.re - a.im * b.im, a.re * b.im + a.im * b.re };
}
__device__ __forceinline__ c2f cadd(c2f a, c2f b) { return { a.re + b.re, a.im + b.im }; }
__device__ __forceinline__ c2f cscale(c2f a, float s) { return { a.re * s, a.im * s }; }
__device__ __forceinline__ c2f cis(float th) {
    float s, c;
    sincosf(th, &s, &c);
    return { c, s };
}

// 1-D FrFT for N=3, fully unrolled (validated in R4's passing kernel).
__device__ __forceinline__ void frft3(c2f& v0, c2f& v1, c2f& v2,
                                      c2f c1a, c2f c1b, c2f c2a, c2f c2b,
                                      float scl) {
    const c2f w  = { -0.5f, -0.8660254037844386f };
    const c2f wb = { -0.5f,  0.8660254037844386f };

    c2f u0 = cmul(v1, c1a);
    c2f u1 = cmul(v2, c1b);
    c2f u2 = v0;

    c2f F0 = cadd(cadd(u0, u1), u2);
    c2f F1 = cadd(cadd(u0, cmul(u1, w )), cmul(u2, wb));
    c2f F2 = cadd(cadd(u0, cmul(u1, wb)), cmul(u2, w ));

    c2f G0 = cmul(F0, c2a);
    c2f G1 = cmul(F1, c2b);
    c2f G2 = F2;

    c2f y0 = cadd(cadd(G0, G1), G2);
    c2f y1 = cadd(cadd(G0, cmul(G1, wb)), cmul(G2, w ));
    c2f y2 = cadd(cadd(G0, cmul(G1, w )), cmul(G2, wb));

    float t3 = scl * (1.0f / 3.0f);
    c2f z0 = cscale(cmul(y0, c1a), t3);
    c2f z1 = cscale(cmul(y1, c1b), t3);
    c2f z2 = cscale(y2, t3);

    v0 = z2; v1 = z0; v2 = z1;
}

// ----------------------------- weight generation ----------------------------
__global__ void frfd_wgen_kernel(const float* __restrict__ spec,
                                 const float* __restrict__ alphap,
                                 const float* __restrict__ polarw) {
    int id = blockIdx.x * blockDim.x + threadIdx.x;
    if (id >= 64 * 64) return;

    float a = alphap[0];
    a = fminf(fmaxf(a, 1e-4f), 2.0f - 1e-4f);

    float t  = tanf(a * PI_F * 0.25f);
    float sa = sinf(a * PI_F * 0.5f);
    float scl = rsqrtf(fabsf(sa) + 1e-12f);

    c2f c1a = cis(-PI_F * 4.0f * t * (1.0f / 3.0f));
    c2f c1b = cis(-PI_F * t * (1.0f / 3.0f));
    float inv3sa = 1.0f / (3.0f * sa);
    c2f c2a = cis(-PI_F * 4.0f * inv3sa);
    c2f c2b = cis(-PI_F * inv3sa);

    c2f Z[3][3];
    const float* sp = spec + (size_t)id * 9;
#pragma unroll
    for (int i = 0; i < 3; i++)
#pragma unroll
        for (int j = 0; j < 3; j++)
            Z[i][j] = { sp[i * 3 + j], 0.0f };

#pragma unroll
    for (int i = 0; i < 3; i++)
        frft3(Z[i][0], Z[i][1], Z[i][2], c1a, c1b, c2a, c2b, scl);
#pragma unroll
    for (int j = 0; j < 3; j++)
        frft3(Z[0][j], Z[1][j], Z[2][j], c1a, c1b, c2a, c2b, scl);

    float pw0 = polarw[0];
    float pw1 = polarw[1];
    ull* gw = g_w2 + (size_t)id * 9;
#pragma unroll
    for (int i = 0; i < 3; i++)
#pragma unroll
        for (int j = 0; j < 3; j++) {
            float re = Z[i][j].re, im = Z[i][j].im;
            float mag = sqrtf(re * re + im * im);
            float ang = atan2f(im, re);
            float k = pw0 * mag + pw1 * (ang * (1.0f / PI_F));
            ull d;
            asm("mov.b64 %0, {%1, %1};" : "=l"(d) : "f"(k));
            gw[i * 3 + j] = d;
        }
}

// --------------------------------- conv3x3 ----------------------------------
// N=16, C=64 -> CO=64, H=W=224, pad 1.
// Block (16,8)=128 threads; tile 32x32 spatial x 8 co.
// Thread: 2 cols (f32x2) x 4 rows x 8 co = 32 packed accumulators.
// grid = (7, 7, 16*8); blockIdx.z = n*8 + cog.

__device__ __forceinline__ void fma2(ull& d, ull a, ull b) {
    asm("fma.rn.f32x2 %0, %1, %2, %0;" : "+l"(d) : "l"(a), "l"(b));
}

__global__ __launch_bounds__(128, 4)
void frfd_conv3x3_kernel(const float* __restrict__ x, float* __restrict__ out) {
    __shared__ __align__(16) float sPatch[2][34 * 34 + 2];   // double buffer
    __shared__ __align__(16) ull   sW[8 * 64 * 9];           // duplicated pairs

    const int tx  = threadIdx.x;       // 0..15 -> column pair
    const int ty  = threadIdx.y;       // 0..7  -> 4-row group
    const int tid = ty * 16 + tx;
    const int bz  = blockIdx.z;
    const int n   = bz >> 3;
    const int cog = bz & 7;

    // stage this block's duplicated weights (36 KB), 16B chunks
    {
        const ulonglong2* src =
            reinterpret_cast<const ulonglong2*>(g_w2 + (size_t)cog * (8 * 64 * 9));
        ulonglong2* dst = reinterpret_cast<ulonglong2*>(sW);
#pragma unroll 3
        for (int i = tid; i < (8 * 64 * 9) / 2; i += 128) dst[i] = src[i];
    }

    const int hb = blockIdx.y * 32;
    const int wb = blockIdx.x * 32;

    // -------- hoisted staging offsets: identical for every ci --------
    int goff[10];
#pragma unroll
    for (int k = 0; k < 10; ++k) {
        int idx = tid + k * 128;
        int pr  = idx / 34;
        int pc  = idx - pr * 34;
        int gh  = hb - 1 + pr;
        int gw2 = wb - 1 + pc;
        bool ok = (idx < 1156) && ((unsigned)gh < 224u) && ((unsigned)gw2 < 224u);
        goff[k] = ok ? gh * 224 + gw2 : -1;
    }

    const float* xn = x + (size_t)n * 64 * 224 * 224;

    // -------- prologue: stage ci = 0 into buffer 0 --------
    float v[10];
    {
        const float* xc = xn;
#pragma unroll
        for (int k = 0; k < 10; ++k)
            v[k] = (goff[k] >= 0) ? xc[goff[k]] : 0.0f;
#pragma unroll
        for (int k = 0; k < 9; ++k) sPatch[0][tid + k * 128] = v[k];
        if (tid < 4) sPatch[0][tid + 1152] = v[9];
    }
    __syncthreads();   // also orders the sW staging

    ull acc[8][4];
#pragma unroll
    for (int co = 0; co < 8; ++co)
#pragma unroll
        for (int rr = 0; rr < 4; ++rr) acc[co][rr] = 0ULL;

    for (int ci = 0; ci < 64; ++ci) {
        const int cur = ci & 1;

        // ---- prefetch ci+1 into registers (overlaps with compute) ----
        if (ci < 63) {
            const float* xc = xn + (size_t)(ci + 1) * (224 * 224);
#pragma unroll
            for (int k = 0; k < 10; ++k)
                v[k] = (goff[k] >= 0) ? xc[goff[k]] : 0.0f;
        }

        // ---- thread window: 6 rows of packed column pairs ----
        ull A[6], B[6], P[6];
#pragma unroll
        for (int r = 0; r < 6; ++r) {
            const float* rowp = &sPatch[cur][(4 * ty + r) * 34 + 2 * tx];
            A[r] = *reinterpret_cast<const ull*>(rowp);
            B[r] = *reinterpret_cast<const ull*>(rowp + 2);
            P[r] = (A[r] >> 32) | (B[r] << 32);
        }

        // ---- 8 co x 4 rows x 9 taps, weights via LDS.64 broadcast ----
        const ull* wci = sW + ci * 9;
#pragma unroll
        for (int co = 0; co < 8; ++co) {
            const ull* wp = wci + co * (64 * 9);
#pragma unroll
            for (int kh = 0; kh < 3; ++kh) {
                ull w0 = wp[kh * 3 + 0];
                ull w1 = wp[kh * 3 + 1];
                ull w2 = wp[kh * 3 + 2];
#pragma unroll
                for (int rr = 0; rr < 4; ++rr) {
                    fma2(acc[co][rr], A[rr + kh], w0);
                    fma2(acc[co][rr], P[rr + kh], w1);
                    fma2(acc[co][rr], B[rr + kh], w2);
                }
            }
        }

        // ---- store prefetched patch into the other buffer ----
        if (ci < 63) {
            float* dstp = sPatch[cur ^ 1];
#pragma unroll
            for (int k = 0; k < 9; ++k) dstp[tid + k * 128] = v[k];
            if (tid < 4) dstp[tid + 1152] = v[9];
        }
        __syncthreads();   // one barrier per ci
    }

    // ---- store: packed pair = contiguous (w, w+1) floats ----
#pragma unroll
    for (int co = 0; co < 8; ++co) {
        size_t cbase = ((size_t)n * 64 + (size_t)cog * 8 + co) * (224 * 224);
#pragma unroll
        for (int rr = 0; rr < 4; ++rr) {
            int h = hb + 4 * ty + rr;
            int w = wb + 2 * tx;
            *reinterpret_cast<ull*>(&out[cbase + (size_t)h * 224 + w]) = acc[co][rr];
        }
    }
}

// --------------------------------- launcher ---------------------------------
extern "C" void kernel_launch(void* const* d_in, const int* in_sizes, int n_in,
                              void* d_out, int out_size) {
    int ix = 0, ispec = 1, ialpha = 2, ipw = 3;
    for (int i = 0; i < n_in; ++i) {
        int s = in_sizes[i];
        if (s == 16 * 64 * 224 * 224) ix = i;
        else if (s == 64 * 64 * 3 * 3) ispec = i;
        else if (s == 1) ialpha = i;
        else if (s == 2) ipw = i;
    }
    const float* x     = (const float*)d_in[ix];
    const float* spec  = (const float*)d_in[ispec];
    const float* alpha = (const float*)d_in[ialpha];
    const float* pw    = (const float*)d_in[ipw];
    float* out = (float*)d_out;

    frfd_wgen_kernel<<<16, 256>>>(spec, alpha, pw);

    dim3 grid(7, 7, 16 * 8);
    dim3 block(16, 8);
    frfd_conv3x3_kernel<<<grid, block>>>(x, out);
}

// round 10
// speedup vs baseline: 3.3283x; 3.3283x over previous
#include <cuda_runtime.h>

// ============================================================================
// FrFDConv via tf32 tensor-core implicit GEMM (mma.sync m16n8k8).
//   GEMM: M = 16*224*224 spatial, N = 64 co, K = 64 ci * 9 taps = 576.
//   Block: M=256 (8h x 32w), N=64, 256 threads (8 warps), warp = 2m x 8n tiles.
//   K loop: 8 chunks of 8 ci (72 k = 9 mma-k-steps, exact fit).
//   Weights pre-swizzled into mma B-fragment order at generation time.
// ============================================================================

#define PI_F 3.14159265358979323846f
typedef unsigned int u32;

// K[co][k], k = ci*9 + tap (fp32)
__device__ float g_wK[64 * 576];
// B fragments, tf32 bits: [kt(72)][nt(8)][lane(32)][2]
__device__ u32 g_Bfrag[72 * 8 * 32 * 2];

// ------------------------------ complex helpers -----------------------------
struct c2f { float re, im; };
__device__ __forceinline__ c2f cmul(c2f a, c2f b) {
    return { a.re * b.re - a.im * b.im, a.re * b.im + a.im * b.re };
}
__device__ __forceinline__ c2f cadd(c2f a, c2f b) { return { a.re + b.re, a.im + b.im }; }
__device__ __forceinline__ c2f cscale(c2f a, float s) { return { a.re * s, a.im * s }; }
__device__ __forceinline__ c2f cis(float th) {
    float s, c; sincosf(th, &s, &c); return { c, s };
}

// 1-D FrFT for N=3 (validated in prior passing kernels).
__device__ __forceinline__ void frft3(c2f& v0, c2f& v1, c2f& v2,
                                      c2f c1a, c2f c1b, c2f c2a, c2f c2b,
                                      float scl) {
    const c2f w  = { -0.5f, -0.8660254037844386f };
    const c2f wb = { -0.5f,  0.8660254037844386f };
    c2f u0 = cmul(v1, c1a);
    c2f u1 = cmul(v2, c1b);
    c2f u2 = v0;
    c2f F0 = cadd(cadd(u0, u1), u2);
    c2f F1 = cadd(cadd(u0, cmul(u1, w )), cmul(u2, wb));
    c2f F2 = cadd(cadd(u0, cmul(u1, wb)), cmul(u2, w ));
    c2f G0 = cmul(F0, c2a);
    c2f G1 = cmul(F1, c2b);
    c2f G2 = F2;
    c2f y0 = cadd(cadd(G0, G1), G2);
    c2f y1 = cadd(cadd(G0, cmul(G1, wb)), cmul(G2, w ));
    c2f y2 = cadd(cadd(G0, cmul(G1, w )), cmul(G2, wb));
    float t3 = scl * (1.0f / 3.0f);
    c2f z0 = cscale(cmul(y0, c1a), t3);
    c2f z1 = cscale(cmul(y1, c1b), t3);
    c2f z2 = cscale(y2, t3);
    v0 = z2; v1 = z0; v2 = z1;
}

// ----------------------------- weight generation ----------------------------
__global__ void frfd_wgen_kernel(const float* __restrict__ spec,
                                 const float* __restrict__ alphap,
                                 const float* __restrict__ polarw) {
    int id = blockIdx.x * blockDim.x + threadIdx.x;
    if (id >= 64 * 64) return;

    float a = alphap[0];
    a = fminf(fmaxf(a, 1e-4f), 2.0f - 1e-4f);
    float t  = tanf(a * PI_F * 0.25f);
    float sa = sinf(a * PI_F * 0.5f);
    float scl = rsqrtf(fabsf(sa) + 1e-12f);
    c2f c1a = cis(-PI_F * 4.0f * t * (1.0f / 3.0f));
    c2f c1b = cis(-PI_F * t * (1.0f / 3.0f));
    float inv3sa = 1.0f / (3.0f * sa);
    c2f c2a = cis(-PI_F * 4.0f * inv3sa);
    c2f c2b = cis(-PI_F * inv3sa);

    c2f Z[3][3];
    const float* sp = spec + (size_t)id * 9;
#pragma unroll
    for (int i = 0; i < 3; i++)
#pragma unroll
        for (int j = 0; j < 3; j++)
            Z[i][j] = { sp[i * 3 + j], 0.0f };
#pragma unroll
    for (int i = 0; i < 3; i++)
        frft3(Z[i][0], Z[i][1], Z[i][2], c1a, c1b, c2a, c2b, scl);
#pragma unroll
    for (int j = 0; j < 3; j++)
        frft3(Z[0][j], Z[1][j], Z[2][j], c1a, c1b, c2a, c2b, scl);

    float pw0 = polarw[0];
    float pw1 = polarw[1];
    int co = id >> 6, ci = id & 63;
    float* gw = g_wK + co * 576 + ci * 9;
#pragma unroll
    for (int i = 0; i < 3; i++)
#pragma unroll
        for (int j = 0; j < 3; j++) {
            float re = Z[i][j].re, im = Z[i][j].im;
            float mag = sqrtf(re * re + im * im);
            float ang = atan2f(im, re);
            gw[i * 3 + j] = pw0 * mag + pw1 * (ang * (1.0f / PI_F));
        }
}

// ---------------- B-fragment swizzle: g_wK -> g_Bfrag (tf32) ----------------
// mma m16n8k8 B fragment: b0 = B[k = kt*8+tig][n = nt*8+gid], b1 = B[k+4][n],
// with B[k][n] = g_wK[n*576 + k].
__global__ void frfd_bfrag_kernel() {
    int kt  = blockIdx.x;           // 0..71
    int tid = threadIdx.x;          // 256 = 8 nt * 32 lanes
    int nt   = tid >> 5;
    int lane = tid & 31;
    int gid  = lane >> 2;
    int tig  = lane & 3;
    int co = nt * 8 + gid;
    int k0 = kt * 8 + tig;
    float v0 = g_wK[co * 576 + k0];
    float v1 = g_wK[co * 576 + k0 + 4];
    u32 t0, t1;
    asm("cvt.rna.tf32.f32 %0, %1;" : "=r"(t0) : "f"(v0));
    asm("cvt.rna.tf32.f32 %0, %1;" : "=r"(t1) : "f"(v1));
    int base = ((kt * 8 + nt) * 32 + lane) * 2;
    g_Bfrag[base]     = t0;
    g_Bfrag[base + 1] = t1;
}

// --------------------------------- conv mma ---------------------------------
__device__ __forceinline__ void mma8(float* c,
                                     u32 a0, u32 a1, u32 a2, u32 a3,
                                     u32 b0, u32 b1) {
    asm volatile(
        "mma.sync.aligned.m16n8k8.row.col.f32.tf32.tf32.f32 "
        "{%0,%1,%2,%3}, {%4,%5,%6,%7}, {%8,%9}, {%0,%1,%2,%3};"
        : "+f"(c[0]), "+f"(c[1]), "+f"(c[2]), "+f"(c[3])
        : "r"(a0), "r"(a1), "r"(a2), "r"(a3), "r"(b0), "r"(b1));
}

__global__ __launch_bounds__(256, 2)
void frfd_conv_mma(const float* __restrict__ x, float* __restrict__ out) {
    // [ci(8)][row(10)][col(36, 34 used)] tf32 bits
    __shared__ __align__(16) u32 sA[8 * 10 * 36];
    // [ktl(9)][nt(8)][lane(32)][2]
    __shared__ __align__(16) u32 sB[9 * 8 * 32 * 2];

    const int tid  = threadIdx.x;
    const int wz   = tid >> 5;        // warp 0..7 -> h row within tile
    const int lane = tid & 31;
    const int gid  = lane >> 2;
    const int tig  = lane & 3;

    const int w0 = blockIdx.x * 32;
    const int h0 = blockIdx.y * 8;
    const int n  = blockIdx.z;

    // per-thread A offsets for the 9 local k-steps (identical every chunk):
    // kl = ktl*8 + tig (+4); ci = kl/9; tap = kl%9 -> (kh,kw);
    // word offset = ci*360 + kh*36 + kw, packed lo|hi<<16.
    u32 dApack[9];
#pragma unroll
    for (int kt = 0; kt < 9; ++kt) {
        int kl = kt * 8 + tig;
        int ci = kl / 9, tap = kl - ci * 9;
        int lo = ci * 360 + (tap / 3) * 36 + (tap % 3);
        int kl2 = kl + 4;
        int ci2 = kl2 / 9, tap2 = kl2 - ci2 * 9;
        int hi = ci2 * 360 + (tap2 / 3) * 36 + (tap2 % 3);
        dApack[kt] = (u32)lo | ((u32)hi << 16);
    }

    float acc[2][8][4];
#pragma unroll
    for (int m = 0; m < 2; ++m)
#pragma unroll
        for (int nt = 0; nt < 8; ++nt)
#pragma unroll
            for (int c = 0; c < 4; ++c) acc[m][nt][c] = 0.0f;

    const float* xb = x + (size_t)n * 64 * 50176;
    const int tBase = wz * 36 + gid;   // spatial base word within patch

    for (int ch = 0; ch < 8; ++ch) {
        __syncthreads();   // previous chunk's reads done

        // ---- stage B fragments for this chunk: 9 kt * 512 u32 = 1152 uint4
        {
            const uint4* src = reinterpret_cast<const uint4*>(g_Bfrag + ch * 4608);
            uint4* dst = reinterpret_cast<uint4*>(sB);
#pragma unroll 5
            for (int i = tid; i < 1152; i += 256) dst[i] = src[i];
        }

        // ---- stage 8-ci patch set (10 x 34 each), tf32-converted
        {
            const int ci0 = ch * 8;
            for (int idx = tid; idx < 2720; idx += 256) {
                int ci  = idx / 340;
                int rem = idx - ci * 340;
                int r   = rem / 34;
                int c   = rem - r * 34;
                int gh = h0 - 1 + r;
                int gw = w0 - 1 + c;
                float v = 0.0f;
                if ((unsigned)gh < 224u && (unsigned)gw < 224u)
                    v = xb[(size_t)(ci0 + ci) * 50176 + gh * 224 + gw];
                u32 tv;
                asm("cvt.rna.tf32.f32 %0, %1;" : "=r"(tv) : "f"(v));
                sA[ci * 360 + r * 36 + c] = tv;
            }
        }
        __syncthreads();

        // ---- 9 k-steps x (2 m-tiles x 8 n-tiles) mma
#pragma unroll 3
        for (int kt = 0; kt < 9; ++kt) {
            u32 p = dApack[kt];
            const u32* aLo = sA + tBase + (p & 0xFFFFu);
            const u32* aHi = sA + tBase + (p >> 16);
            u32 a0 = aLo[0],  a1 = aLo[8],  a2 = aHi[0],  a3 = aHi[8];
            u32 a4 = aLo[16], a5 = aLo[24], a6 = aHi[16], a7 = aHi[24];
            const u32* bp = sB + kt * 512 + lane * 2;
#pragma unroll
            for (int nt = 0; nt < 8; ++nt) {
                uint2 bb = *reinterpret_cast<const uint2*>(bp + nt * 64);
                mma8(acc[0][nt], a0, a1, a2, a3, bb.x, bb.y);
                mma8(acc[1][nt], a4, a5, a6, a7, bb.x, bb.y);
            }
        }
    }

    // ---- epilogue: scatter stores (32B-sector efficient)
    // c0:(m=gid, co), c1:(m, co+1), c2:(m+8, co), c3:(m+8, co+1)
    const int sp0 = (h0 + wz) * 224 + w0 + gid;
    float* ob = out + (size_t)n * 64 * 50176;
#pragma unroll
    for (int nt = 0; nt < 8; ++nt) {
        int co = nt * 8 + tig * 2;
        float* p0 = ob + (size_t)co * 50176 + sp0;
        float* p1 = p0 + 50176;
#pragma unroll
        for (int mtl = 0; mtl < 2; ++mtl) {
            float* q0 = p0 + mtl * 16;
            float* q1 = p1 + mtl * 16;
            q0[0] = acc[mtl][nt][0];
            q1[0] = acc[mtl][nt][1];
            q0[8] = acc[mtl][nt][2];
            q1[8] = acc[mtl][nt][3];
        }
    }
}

// --------------------------------- launcher ---------------------------------
extern "C" void kernel_launch(void* const* d_in, const int* in_sizes, int n_in,
                              void* d_out, int out_size) {
    int ix = 0, ispec = 1, ialpha = 2, ipw = 3;
    for (int i = 0; i < n_in; ++i) {
        int s = in_sizes[i];
        if (s == 16 * 64 * 224 * 224) ix = i;
        else if (s == 64 * 64 * 3 * 3) ispec = i;
        else if (s == 1) ialpha = i;
        else if (s == 2) ipw = i;
    }
    const float* x     = (const float*)d_in[ix];
    const float* spec  = (const float*)d_in[ispec];
    const float* alpha = (const float*)d_in[ialpha];
    const float* pw    = (const float*)d_in[ipw];
    float* out = (float*)d_out;

    frfd_wgen_kernel<<<16, 256>>>(spec, alpha, pw);
    frfd_bfrag_kernel<<<72, 256>>>();

    dim3 grid(7, 28, 16);
    frfd_conv_mma<<<grid, 256>>>(x, out);
}

// round 11
// speedup vs baseline: 3.8549x; 1.1582x over previous
#include <cuda_runtime.h>

// ============================================================================
// FrFDConv via tf32 tensor-core implicit GEMM (mma.sync m16n8k8).
// R10: (4m x 8n) warp tile (128 acc regs), B fragments via __ldg straight from
// L1/L2 (no smem restage), double-buffered A patches + register prefetch,
// one barrier per k-chunk. 128-thread blocks, 2 blocks/SM.
//   GEMM: M = 16*224*224, N = 64 co, K = 576 (64 ci * 9 taps), chunks of 8 ci.
// ============================================================================

#define PI_F 3.14159265358979323846f
typedef unsigned int u32;

// K[co][k], k = ci*9 + tap (fp32)
__device__ float g_wK[64 * 576];
// B fragments, tf32 bits: [kt(72)][nt(8)][lane(32)][2]
__device__ u32 g_Bfrag[72 * 8 * 32 * 2];

// ------------------------------ complex helpers -----------------------------
struct c2f { float re, im; };
__device__ __forceinline__ c2f cmul(c2f a, c2f b) {
    return { a.re * b.re - a.im * b.im, a.re * b.im + a.im * b.re };
}
__device__ __forceinline__ c2f cadd(c2f a, c2f b) { return { a.re + b.re, a.im + b.im }; }
__device__ __forceinline__ c2f cscale(c2f a, float s) { return { a.re * s, a.im * s }; }
__device__ __forceinline__ c2f cis(float th) {
    float s, c; sincosf(th, &s, &c); return { c, s };
}

__device__ __forceinline__ void frft3(c2f& v0, c2f& v1, c2f& v2,
                                      c2f c1a, c2f c1b, c2f c2a, c2f c2b,
                                      float scl) {
    const c2f w  = { -0.5f, -0.8660254037844386f };
    const c2f wb = { -0.5f,  0.8660254037844386f };
    c2f u0 = cmul(v1, c1a);
    c2f u1 = cmul(v2, c1b);
    c2f u2 = v0;
    c2f F0 = cadd(cadd(u0, u1), u2);
    c2f F1 = cadd(cadd(u0, cmul(u1, w )), cmul(u2, wb));
    c2f F2 = cadd(cadd(u0, cmul(u1, wb)), cmul(u2, w ));
    c2f G0 = cmul(F0, c2a);
    c2f G1 = cmul(F1, c2b);
    c2f G2 = F2;
    c2f y0 = cadd(cadd(G0, G1), G2);
    c2f y1 = cadd(cadd(G0, cmul(G1, wb)), cmul(G2, w ));
    c2f y2 = cadd(cadd(G0, cmul(G1, w )), cmul(G2, wb));
    float t3 = scl * (1.0f / 3.0f);
    c2f z0 = cscale(cmul(y0, c1a), t3);
    c2f z1 = cscale(cmul(y1, c1b), t3);
    c2f z2 = cscale(y2, t3);
    v0 = z2; v1 = z0; v2 = z1;
}

// ----------------------------- weight generation ----------------------------
__global__ void frfd_wgen_kernel(const float* __restrict__ spec,
                                 const float* __restrict__ alphap,
                                 const float* __restrict__ polarw) {
    int id = blockIdx.x * blockDim.x + threadIdx.x;
    if (id >= 64 * 64) return;

    float a = alphap[0];
    a = fminf(fmaxf(a, 1e-4f), 2.0f - 1e-4f);
    float t  = tanf(a * PI_F * 0.25f);
    float sa = sinf(a * PI_F * 0.5f);
    float scl = rsqrtf(fabsf(sa) + 1e-12f);
    c2f c1a = cis(-PI_F * 4.0f * t * (1.0f / 3.0f));
    c2f c1b = cis(-PI_F * t * (1.0f / 3.0f));
    float inv3sa = 1.0f / (3.0f * sa);
    c2f c2a = cis(-PI_F * 4.0f * inv3sa);
    c2f c2b = cis(-PI_F * inv3sa);

    c2f Z[3][3];
    const float* sp = spec + (size_t)id * 9;
#pragma unroll
    for (int i = 0; i < 3; i++)
#pragma unroll
        for (int j = 0; j < 3; j++)
            Z[i][j] = { sp[i * 3 + j], 0.0f };
#pragma unroll
    for (int i = 0; i < 3; i++)
        frft3(Z[i][0], Z[i][1], Z[i][2], c1a, c1b, c2a, c2b, scl);
#pragma unroll
    for (int j = 0; j < 3; j++)
        frft3(Z[0][j], Z[1][j], Z[2][j], c1a, c1b, c2a, c2b, scl);

    float pw0 = polarw[0];
    float pw1 = polarw[1];
    int co = id >> 6, ci = id & 63;
    float* gw = g_wK + co * 576 + ci * 9;
#pragma unroll
    for (int i = 0; i < 3; i++)
#pragma unroll
        for (int j = 0; j < 3; j++) {
            float re = Z[i][j].re, im = Z[i][j].im;
            float mag = sqrtf(re * re + im * im);
            float ang = atan2f(im, re);
            gw[i * 3 + j] = pw0 * mag + pw1 * (ang * (1.0f / PI_F));
        }
}

// ---------------- B-fragment swizzle: g_wK -> g_Bfrag (tf32) ----------------
__global__ void frfd_bfrag_kernel() {
    int kt  = blockIdx.x;           // 0..71
    int tid = threadIdx.x;          // 256 = 8 nt * 32 lanes
    int nt   = tid >> 5;
    int lane = tid & 31;
    int gid  = lane >> 2;
    int tig  = lane & 3;
    int co = nt * 8 + gid;
    int k0 = kt * 8 + tig;
    float v0 = g_wK[co * 576 + k0];
    float v1 = g_wK[co * 576 + k0 + 4];
    u32 t0, t1;
    asm("cvt.rna.tf32.f32 %0, %1;" : "=r"(t0) : "f"(v0));
    asm("cvt.rna.tf32.f32 %0, %1;" : "=r"(t1) : "f"(v1));
    int base = ((kt * 8 + nt) * 32 + lane) * 2;
    g_Bfrag[base]     = t0;
    g_Bfrag[base + 1] = t1;
}

// --------------------------------- conv mma ---------------------------------
__device__ __forceinline__ void mma8(float* c,
                                     u32 a0, u32 a1, u32 a2, u32 a3,
                                     u32 b0, u32 b1) {
    asm volatile(
        "mma.sync.aligned.m16n8k8.row.col.f32.tf32.tf32.f32 "
        "{%0,%1,%2,%3}, {%4,%5,%6,%7}, {%8,%9}, {%0,%1,%2,%3};"
        : "+f"(c[0]), "+f"(c[1]), "+f"(c[2]), "+f"(c[3])
        : "r"(a0), "r"(a1), "r"(a2), "r"(a3), "r"(b0), "r"(b1));
}

__global__ __launch_bounds__(128, 2)
void frfd_conv_mma(const float* __restrict__ x, float* __restrict__ out) {
    // double-buffered A patches: [buf][ci(8)][row(10)][col(36, 34 used)]
    __shared__ __align__(16) u32 sA[2][8 * 10 * 36];

    const int tid  = threadIdx.x;       // 128
    const int wz   = tid >> 5;          // warp 0..3 -> h row pair
    const int lane = tid & 31;
    const int gid  = lane >> 2;
    const int tig  = lane & 3;

    const int w0 = blockIdx.x * 32;
    const int h0 = blockIdx.y * 8;
    const int n  = blockIdx.z;

    // per-thread A word offsets for the 9 local k-steps (same every chunk)
    u32 dApack[9];
#pragma unroll
    for (int kt = 0; kt < 9; ++kt) {
        int kl = kt * 8 + tig;
        int ci = kl / 9, tap = kl - ci * 9;
        int lo = ci * 360 + (tap / 3) * 36 + (tap % 3);
        int kl2 = kl + 4;
        int ci2 = kl2 / 9, tap2 = kl2 - ci2 * 9;
        int hi = ci2 * 360 + (tap2 / 3) * 36 + (tap2 % 3);
        dApack[kt] = (u32)lo | ((u32)hi << 16);
    }

    // 4 m-tile spatial bases: (rh, wt)
    int mBase[2][2];
#pragma unroll
    for (int rh = 0; rh < 2; ++rh)
#pragma unroll
        for (int wt = 0; wt < 2; ++wt)
            mBase[rh][wt] = (2 * wz + rh) * 36 + wt * 16 + gid;

    float acc[2][2][8][4];
#pragma unroll
    for (int rh = 0; rh < 2; ++rh)
#pragma unroll
        for (int wt = 0; wt < 2; ++wt)
#pragma unroll
            for (int nt = 0; nt < 8; ++nt)
#pragma unroll
                for (int c = 0; c < 4; ++c) acc[rh][wt][nt][c] = 0.0f;

    const float* xb = x + (size_t)n * 64 * 50176;

    // ---- prologue: stage chunk 0 into buffer 0 ----
    for (int idx = tid; idx < 2720; idx += 128) {
        int ci  = idx / 340;
        int rem = idx - ci * 340;
        int r   = rem / 34;
        int c   = rem - r * 34;
        int gh = h0 - 1 + r;
        int gw = w0 - 1 + c;
        float v = 0.0f;
        if ((unsigned)gh < 224u && (unsigned)gw < 224u)
            v = __ldg(xb + (size_t)ci * 50176 + gh * 224 + gw);
        u32 tv;
        asm("cvt.rna.tf32.f32 %0, %1;" : "=r"(tv) : "f"(v));
        sA[0][ci * 360 + r * 36 + c] = tv;
    }
    __syncthreads();

    const uint2* bTab = reinterpret_cast<const uint2*>(g_Bfrag);

    for (int ch = 0; ch < 8; ++ch) {
        const u32* __restrict__ aBuf = sA[ch & 1];

        // ---- prefetch chunk ch+1 LDGs into registers (fly during mma) ----
        float vpre[22];
        if (ch < 7) {
            const float* xc = xb + (size_t)(ch + 1) * 8 * 50176;
#pragma unroll
            for (int k = 0; k < 22; ++k) {
                int idx = tid + k * 128;
                float v = 0.0f;
                if (idx < 2720) {
                    int ci  = idx / 340;
                    int rem = idx - ci * 340;
                    int r   = rem / 34;
                    int c   = rem - r * 34;
                    int gh = h0 - 1 + r;
                    int gw = w0 - 1 + c;
                    if ((unsigned)gh < 224u && (unsigned)gw < 224u)
                        v = __ldg(xc + (size_t)ci * 50176 + gh * 224 + gw);
                }
                vpre[k] = v;
            }
        }

        // ---- 9 k-steps x (4 m-tiles x 8 n-tiles) mma ----
        const uint2* bChunk = bTab + (size_t)ch * 9 * 8 * 32 + lane;
#pragma unroll 3
        for (int kt = 0; kt < 9; ++kt) {
            u32 p = dApack[kt];
            const u32* aLo = aBuf + (p & 0xFFFFu);
            const u32* aHi = aBuf + (p >> 16);
            u32 a[2][2][4];
#pragma unroll
            for (int rh = 0; rh < 2; ++rh)
#pragma unroll
                for (int wt = 0; wt < 2; ++wt) {
                    int b = mBase[rh][wt];
                    a[rh][wt][0] = aLo[b];
                    a[rh][wt][1] = aLo[b + 8];
                    a[rh][wt][2] = aHi[b];
                    a[rh][wt][3] = aHi[b + 8];
                }
            const uint2* bp = bChunk + (size_t)kt * 256;
#pragma unroll
            for (int nt = 0; nt < 8; ++nt) {
                uint2 bb = __ldg(bp + nt * 32);
#pragma unroll
                for (int rh = 0; rh < 2; ++rh)
#pragma unroll
                    for (int wt = 0; wt < 2; ++wt)
                        mma8(acc[rh][wt][nt],
                             a[rh][wt][0], a[rh][wt][1],
                             a[rh][wt][2], a[rh][wt][3],
                             bb.x, bb.y);
            }
        }

        // ---- store prefetched chunk into the other buffer ----
        if (ch < 7) {
            u32* dst = sA[(ch + 1) & 1];
#pragma unroll
            for (int k = 0; k < 22; ++k) {
                int idx = tid + k * 128;
                if (idx < 2720) {
                    int ci  = idx / 340;
                    int rem = idx - ci * 340;
                    int r   = rem / 34;
                    int c   = rem - r * 34;
                    u32 tv;
                    asm("cvt.rna.tf32.f32 %0, %1;" : "=r"(tv) : "f"(vpre[k]));
                    dst[ci * 360 + r * 36 + c] = tv;
                }
            }
        }
        __syncthreads();
    }

    // ---- epilogue: scatter stores (32B-sector aligned groups) ----
    float* ob = out + (size_t)n * 64 * 50176;
#pragma unroll
    for (int nt = 0; nt < 8; ++nt) {
        int co = nt * 8 + tig * 2;
#pragma unroll
        for (int rh = 0; rh < 2; ++rh) {
            int h = h0 + 2 * wz + rh;
            float* p0 = ob + (size_t)co * 50176 + h * 224 + w0 + gid;
            float* p1 = p0 + 50176;
#pragma unroll
            for (int wt = 0; wt < 2; ++wt) {
                float* q0 = p0 + wt * 16;
                float* q1 = p1 + wt * 16;
                q0[0] = acc[rh][wt][nt][0];
                q1[0] = acc[rh][wt][nt][1];
                q0[8] = acc[rh][wt][nt][2];
                q1[8] = acc[rh][wt][nt][3];
            }
        }
    }
}

// --------------------------------- launcher ---------------------------------
extern "C" void kernel_launch(void* const* d_in, const int* in_sizes, int n_in,
                              void* d_out, int out_size) {
    int ix = 0, ispec = 1, ialpha = 2, ipw = 3;
    for (int i = 0; i < n_in; ++i) {
        int s = in_sizes[i];
        if (s == 16 * 64 * 224 * 224) ix = i;
        else if (s == 64 * 64 * 3 * 3) ispec = i;
        else if (s == 1) ialpha = i;
        else if (s == 2) ipw = i;
    }
    const float* x     = (const float*)d_in[ix];
    const float* spec  = (const float*)d_in[ispec];
    const float* alpha = (const float*)d_in[ialpha];
    const float* pw    = (const float*)d_in[ipw];
    float* out = (float*)d_out;

    frfd_wgen_kernel<<<16, 256>>>(spec, alpha, pw);
    frfd_bfrag_kernel<<<72, 256>>>();

    dim3 grid(7, 28, 16);
    frfd_conv_mma<<<grid, 128>>>(x, out);
}

// round 12
// speedup vs baseline: 3.9630x; 1.0280x over previous
#include <cuda_runtime.h>

// ============================================================================
// FrFDConv via tf32 tensor-core implicit GEMM (mma.sync m16n8k8).
// R11: tap-major K permutation -> the four tig-groups of every A-fragment LDS
// land at word offsets differing by 360 (== 8 mod 32), making all A shared-
// memory loads bank-conflict-free. B fragment table regenerated to match.
//   GEMM: M = 16*224*224, N = 64 co, K = 576; chunks of 8 ci (72 k / chunk).
//   k-step kt (0..8) <-> tap kt;  k(tig) = (tap, ci=tig), k(tig+4) = (tap, ci=4+tig).
// ============================================================================

#define PI_F 3.14159265358979323846f
typedef unsigned int u32;

// K[co][k], k = ci*9 + tap (fp32)
__device__ float g_wK[64 * 576];
// B fragments, tf32 bits: [ktg(72)][nt(8)][lane(32)][2]
__device__ u32 g_Bfrag[72 * 8 * 32 * 2];

// ------------------------------ complex helpers -----------------------------
struct c2f { float re, im; };
__device__ __forceinline__ c2f cmul(c2f a, c2f b) {
    return { a.re * b.re - a.im * b.im, a.re * b.im + a.im * b.re };
}
__device__ __forceinline__ c2f cadd(c2f a, c2f b) { return { a.re + b.re, a.im + b.im }; }
__device__ __forceinline__ c2f cscale(c2f a, float s) { return { a.re * s, a.im * s }; }
__device__ __forceinline__ c2f cis(float th) {
    float s, c; sincosf(th, &s, &c); return { c, s };
}

__device__ __forceinline__ void frft3(c2f& v0, c2f& v1, c2f& v2,
                                      c2f c1a, c2f c1b, c2f c2a, c2f c2b,
                                      float scl) {
    const c2f w  = { -0.5f, -0.8660254037844386f };
    const c2f wb = { -0.5f,  0.8660254037844386f };
    c2f u0 = cmul(v1, c1a);
    c2f u1 = cmul(v2, c1b);
    c2f u2 = v0;
    c2f F0 = cadd(cadd(u0, u1), u2);
    c2f F1 = cadd(cadd(u0, cmul(u1, w )), cmul(u2, wb));
    c2f F2 = cadd(cadd(u0, cmul(u1, wb)), cmul(u2, w ));
    c2f G0 = cmul(F0, c2a);
    c2f G1 = cmul(F1, c2b);
    c2f G2 = F2;
    c2f y0 = cadd(cadd(G0, G1), G2);
    c2f y1 = cadd(cadd(G0, cmul(G1, wb)), cmul(G2, w ));
    c2f y2 = cadd(cadd(G0, cmul(G1, w )), cmul(G2, wb));
    float t3 = scl * (1.0f / 3.0f);
    c2f z0 = cscale(cmul(y0, c1a), t3);
    c2f z1 = cscale(cmul(y1, c1b), t3);
    c2f z2 = cscale(y2, t3);
    v0 = z2; v1 = z0; v2 = z1;
}

// ----------------------------- weight generation ----------------------------
__global__ void frfd_wgen_kernel(const float* __restrict__ spec,
                                 const float* __restrict__ alphap,
                                 const float* __restrict__ polarw) {
    int id = blockIdx.x * blockDim.x + threadIdx.x;
    if (id >= 64 * 64) return;

    float a = alphap[0];
    a = fminf(fmaxf(a, 1e-4f), 2.0f - 1e-4f);
    float t  = tanf(a * PI_F * 0.25f);
    float sa = sinf(a * PI_F * 0.5f);
    float scl = rsqrtf(fabsf(sa) + 1e-12f);
    c2f c1a = cis(-PI_F * 4.0f * t * (1.0f / 3.0f));
    c2f c1b = cis(-PI_F * t * (1.0f / 3.0f));
    float inv3sa = 1.0f / (3.0f * sa);
    c2f c2a = cis(-PI_F * 4.0f * inv3sa);
    c2f c2b = cis(-PI_F * inv3sa);

    c2f Z[3][3];
    const float* sp = spec + (size_t)id * 9;
#pragma unroll
    for (int i = 0; i < 3; i++)
#pragma unroll
        for (int j = 0; j < 3; j++)
            Z[i][j] = { sp[i * 3 + j], 0.0f };
#pragma unroll
    for (int i = 0; i < 3; i++)
        frft3(Z[i][0], Z[i][1], Z[i][2], c1a, c1b, c2a, c2b, scl);
#pragma unroll
    for (int j = 0; j < 3; j++)
        frft3(Z[0][j], Z[1][j], Z[2][j], c1a, c1b, c2a, c2b, scl);

    float pw0 = polarw[0];
    float pw1 = polarw[1];
    int co = id >> 6, ci = id & 63;
    float* gw = g_wK + co * 576 + ci * 9;
#pragma unroll
    for (int i = 0; i < 3; i++)
#pragma unroll
        for (int j = 0; j < 3; j++) {
            float re = Z[i][j].re, im = Z[i][j].im;
            float mag = sqrtf(re * re + im * im);
            float ang = atan2f(im, re);
            gw[i * 3 + j] = pw0 * mag + pw1 * (ang * (1.0f / PI_F));
        }
}

// ---------------- B-fragment swizzle: g_wK -> g_Bfrag (tf32) ----------------
// Tap-major K order: global k-step ktg = ch*9 + tap.
//   b0 = W[co][ci = ch*8 + tig][tap],  b1 = W[co][ci = ch*8 + 4 + tig][tap]
__global__ void frfd_bfrag_kernel() {
    int ktg = blockIdx.x;           // 0..71
    int tid = threadIdx.x;          // 256 = 8 nt * 32 lanes
    int nt   = tid >> 5;
    int lane = tid & 31;
    int gid  = lane >> 2;
    int tig  = lane & 3;
    int ch  = ktg / 9;
    int tap = ktg - ch * 9;
    int co  = nt * 8 + gid;
    int ci0 = ch * 8 + tig;
    float v0 = g_wK[co * 576 + ci0 * 9 + tap];
    float v1 = g_wK[co * 576 + (ci0 + 4) * 9 + tap];
    u32 t0, t1;
    asm("cvt.rna.tf32.f32 %0, %1;" : "=r"(t0) : "f"(v0));
    asm("cvt.rna.tf32.f32 %0, %1;" : "=r"(t1) : "f"(v1));
    int base = ((ktg * 8 + nt) * 32 + lane) * 2;
    g_Bfrag[base]     = t0;
    g_Bfrag[base + 1] = t1;
}

// --------------------------------- conv mma ---------------------------------
__device__ __forceinline__ void mma8(float* c,
                                     u32 a0, u32 a1, u32 a2, u32 a3,
                                     u32 b0, u32 b1) {
    asm volatile(
        "mma.sync.aligned.m16n8k8.row.col.f32.tf32.tf32.f32 "
        "{%0,%1,%2,%3}, {%4,%5,%6,%7}, {%8,%9}, {%0,%1,%2,%3};"
        : "+f"(c[0]), "+f"(c[1]), "+f"(c[2]), "+f"(c[3])
        : "r"(a0), "r"(a1), "r"(a2), "r"(a3), "r"(b0), "r"(b1));
}

__global__ __launch_bounds__(128, 2)
void frfd_conv_mma(const float* __restrict__ x, float* __restrict__ out) {
    // double-buffered A patches: [buf][ci(8)][row(10)][col(36, 34 used)]
    __shared__ __align__(16) u32 sA[2][8 * 10 * 36];

    const int tid  = threadIdx.x;       // 128
    const int wz   = tid >> 5;          // warp 0..3 -> h row pair
    const int lane = tid & 31;
    const int gid  = lane >> 2;
    const int tig  = lane & 3;

    const int w0 = blockIdx.x * 32;
    const int h0 = blockIdx.y * 8;
    const int n  = blockIdx.z;

    // Tap-major per-thread A offsets for the 9 k-steps:
    //   kt <-> tap;  lo: ci = tig, hi: ci = tig + 4.
    //   offset = ci*360 + (tap/3)*36 + (tap%3).
    // Within one LDS, tig groups differ by 360 words (== 8 mod 32): conflict-free.
    u32 dApack[9];
#pragma unroll
    for (int kt = 0; kt < 9; ++kt) {
        int tapoff = (kt / 3) * 36 + (kt % 3);
        int lo = tig * 360 + tapoff;
        int hi = lo + 4 * 360;
        dApack[kt] = (u32)lo | ((u32)hi << 16);
    }

    // 4 m-tile spatial bases: (rh, wt)
    int mBase[2][2];
#pragma unroll
    for (int rh = 0; rh < 2; ++rh)
#pragma unroll
        for (int wt = 0; wt < 2; ++wt)
            mBase[rh][wt] = (2 * wz + rh) * 36 + wt * 16 + gid;

    float acc[2][2][8][4];
#pragma unroll
    for (int rh = 0; rh < 2; ++rh)
#pragma unroll
        for (int wt = 0; wt < 2; ++wt)
#pragma unroll
            for (int nt = 0; nt < 8; ++nt)
#pragma unroll
                for (int c = 0; c < 4; ++c) acc[rh][wt][nt][c] = 0.0f;

    const float* xb = x + (size_t)n * 64 * 50176;

    // ---- prologue: stage chunk 0 into buffer 0 ----
    for (int idx = tid; idx < 2720; idx += 128) {
        int ci  = idx / 340;
        int rem = idx - ci * 340;
        int r   = rem / 34;
        int c   = rem - r * 34;
        int gh = h0 - 1 + r;
        int gw = w0 - 1 + c;
        float v = 0.0f;
        if ((unsigned)gh < 224u && (unsigned)gw < 224u)
            v = __ldg(xb + (size_t)ci * 50176 + gh * 224 + gw);
        u32 tv;
        asm("cvt.rna.tf32.f32 %0, %1;" : "=r"(tv) : "f"(v));
        sA[0][ci * 360 + r * 36 + c] = tv;
    }
    __syncthreads();

    const uint2* bTab = reinterpret_cast<const uint2*>(g_Bfrag);

    for (int ch = 0; ch < 8; ++ch) {
        const u32* __restrict__ aBuf = sA[ch & 1];

        // ---- prefetch chunk ch+1 LDGs into registers (fly during mma) ----
        float vpre[22];
        if (ch < 7) {
            const float* xc = xb + (size_t)(ch + 1) * 8 * 50176;
#pragma unroll
            for (int k = 0; k < 22; ++k) {
                int idx = tid + k * 128;
                float v = 0.0f;
                if (idx < 2720) {
                    int ci  = idx / 340;
                    int rem = idx - ci * 340;
                    int r   = rem / 34;
                    int c   = rem - r * 34;
                    int gh = h0 - 1 + r;
                    int gw = w0 - 1 + c;
                    if ((unsigned)gh < 224u && (unsigned)gw < 224u)
                        v = __ldg(xc + (size_t)ci * 50176 + gh * 224 + gw);
                }
                vpre[k] = v;
            }
        }

        // ---- 9 k-steps x (4 m-tiles x 8 n-tiles) mma ----
        const uint2* bChunk = bTab + (size_t)ch * 9 * 8 * 32 + lane;
#pragma unroll 3
        for (int kt = 0; kt < 9; ++kt) {
            u32 p = dApack[kt];
            const u32* aLo = aBuf + (p & 0xFFFFu);
            const u32* aHi = aBuf + (p >> 16);
            u32 a[2][2][4];
#pragma unroll
            for (int rh = 0; rh < 2; ++rh)
#pragma unroll
                for (int wt = 0; wt < 2; ++wt) {
                    int b = mBase[rh][wt];
                    a[rh][wt][0] = aLo[b];
                    a[rh][wt][1] = aLo[b + 8];
                    a[rh][wt][2] = aHi[b];
                    a[rh][wt][3] = aHi[b + 8];
                }
            const uint2* bp = bChunk + (size_t)kt * 256;
#pragma unroll
            for (int nt = 0; nt < 8; ++nt) {
                uint2 bb = __ldg(bp + nt * 32);
#pragma unroll
                for (int rh = 0; rh < 2; ++rh)
#pragma unroll
                    for (int wt = 0; wt < 2; ++wt)
                        mma8(acc[rh][wt][nt],
                             a[rh][wt][0], a[rh][wt][1],
                             a[rh][wt][2], a[rh][wt][3],
                             bb.x, bb.y);
            }
        }

        // ---- store prefetched chunk into the other buffer ----
        if (ch < 7) {
            u32* dst = sA[(ch + 1) & 1];
#pragma unroll
            for (int k = 0; k < 22; ++k) {
                int idx = tid + k * 128;
                if (idx < 2720) {
                    int ci  = idx / 340;
                    int rem = idx - ci * 340;
                    int r   = rem / 34;
                    int c   = rem - r * 34;
                    u32 tv;
                    asm("cvt.rna.tf32.f32 %0, %1;" : "=r"(tv) : "f"(vpre[k]));
                    dst[ci * 360 + r * 36 + c] = tv;
                }
            }
        }
        __syncthreads();
    }

    // ---- epilogue: scatter stores (32B-sector aligned groups) ----
    float* ob = out + (size_t)n * 64 * 50176;
#pragma unroll
    for (int nt = 0; nt < 8; ++nt) {
        int co = nt * 8 + tig * 2;
#pragma unroll
        for (int rh = 0; rh < 2; ++rh) {
            int h = h0 + 2 * wz + rh;
            float* p0 = ob + (size_t)co * 50176 + h * 224 + w0 + gid;
            float* p1 = p0 + 50176;
#pragma unroll
            for (int wt = 0; wt < 2; ++wt) {
                float* q0 = p0 + wt * 16;
                float* q1 = p1 + wt * 16;
                q0[0] = acc[rh][wt][nt][0];
                q1[0] = acc[rh][wt][nt][1];
                q0[8] = acc[rh][wt][nt][2];
                q1[8] = acc[rh][wt][nt][3];
            }
        }
    }
}

// --------------------------------- launcher ---------------------------------
extern "C" void kernel_launch(void* const* d_in, const int* in_sizes, int n_in,
                              void* d_out, int out_size) {
    int ix = 0, ispec = 1, ialpha = 2, ipw = 3;
    for (int i = 0; i < n_in; ++i) {
        int s = in_sizes[i];
        if (s == 16 * 64 * 224 * 224) ix = i;
        else if (s == 64 * 64 * 3 * 3) ispec = i;
        else if (s == 1) ialpha = i;
        else if (s == 2) ipw = i;
    }
    const float* x     = (const float*)d_in[ix];
    const float* spec  = (const float*)d_in[ispec];
    const float* alpha = (const float*)d_in[ialpha];
    const float* pw    = (const float*)d_in[ipw];
    float* out = (float*)d_out;

    frfd_wgen_kernel<<<16, 256>>>(spec, alpha, pw);
    frfd_bfrag_kernel<<<72, 256>>>();

    dim3 grid(7, 28, 16);
    frfd_conv_mma<<<grid, 128>>>(x, out);
}

// round 13
// speedup vs baseline: 6.3238x; 1.5957x over previous
#include <cuda_runtime.h>
#include <cuda_fp16.h>

// ============================================================================
// FrFDConv via fp16 tensor-core implicit GEMM (mma.sync m16n8k16.f16, f32 acc).
// R13: tf32 -> fp16 operands. Same 10-bit mantissa => same ~3e-4 error class,
// but K=16 per mma halves the tensor instruction count (28.9M -> 14.45M).
//   GEMM: M = 16*224*224, N = 64 co, K = 576 = 4 chunks * 16 ci * 9 taps.
//   k16-step = tap; k-within-step = local ci (A stored as half2 ci-pairs).
//   A-LDS stays bank-conflict-free: tig stride 360 words == 8 mod 32.
// ============================================================================

#define PI_F 3.14159265358979323846f
typedef unsigned int u32;

// K[co][k], k = ci*9 + tap (fp32)
__device__ float g_wK[64 * 576];
// B fragments: [s(36)][nt(8)][lane(32)] -> uint2 {b0(half2), b1(half2)}
__device__ uint2 g_BfragH[36 * 8 * 32];

// ------------------------------ complex helpers -----------------------------
struct c2f { float re, im; };
__device__ __forceinline__ c2f cmul(c2f a, c2f b) {
    return { a.re * b.re - a.im * b.im, a.re * b.im + a.im * b.re };
}
__device__ __forceinline__ c2f cadd(c2f a, c2f b) { return { a.re + b.re, a.im + b.im }; }
__device__ __forceinline__ c2f cscale(c2f a, float s) { return { a.re * s, a.im * s }; }
__device__ __forceinline__ c2f cis(float th) {
    float s, c; sincosf(th, &s, &c); return { c, s };
}

__device__ __forceinline__ void frft3(c2f& v0, c2f& v1, c2f& v2,
                                      c2f c1a, c2f c1b, c2f c2a, c2f c2b,
                                      float scl) {
    const c2f w  = { -0.5f, -0.8660254037844386f };
    const c2f wb = { -0.5f,  0.8660254037844386f };
    c2f u0 = cmul(v1, c1a);
    c2f u1 = cmul(v2, c1b);
    c2f u2 = v0;
    c2f F0 = cadd(cadd(u0, u1), u2);
    c2f F1 = cadd(cadd(u0, cmul(u1, w )), cmul(u2, wb));
    c2f F2 = cadd(cadd(u0, cmul(u1, wb)), cmul(u2, w ));
    c2f G0 = cmul(F0, c2a);
    c2f G1 = cmul(F1, c2b);
    c2f G2 = F2;
    c2f y0 = cadd(cadd(G0, G1), G2);
    c2f y1 = cadd(cadd(G0, cmul(G1, wb)), cmul(G2, w ));
    c2f y2 = cadd(cadd(G0, cmul(G1, w )), cmul(G2, wb));
    float t3 = scl * (1.0f / 3.0f);
    c2f z0 = cscale(cmul(y0, c1a), t3);
    c2f z1 = cscale(cmul(y1, c1b), t3);
    c2f z2 = cscale(y2, t3);
    v0 = z2; v1 = z0; v2 = z1;
}

// ----------------------------- weight generation ----------------------------
__global__ void frfd_wgen_kernel(const float* __restrict__ spec,
                                 const float* __restrict__ alphap,
                                 const float* __restrict__ polarw) {
    int id = blockIdx.x * blockDim.x + threadIdx.x;
    if (id >= 64 * 64) return;

    float a = alphap[0];
    a = fminf(fmaxf(a, 1e-4f), 2.0f - 1e-4f);
    float t  = tanf(a * PI_F * 0.25f);
    float sa = sinf(a * PI_F * 0.5f);
    float scl = rsqrtf(fabsf(sa) + 1e-12f);
    c2f c1a = cis(-PI_F * 4.0f * t * (1.0f / 3.0f));
    c2f c1b = cis(-PI_F * t * (1.0f / 3.0f));
    float inv3sa = 1.0f / (3.0f * sa);
    c2f c2a = cis(-PI_F * 4.0f * inv3sa);
    c2f c2b = cis(-PI_F * inv3sa);

    c2f Z[3][3];
    const float* sp = spec + (size_t)id * 9;
#pragma unroll
    for (int i = 0; i < 3; i++)
#pragma unroll
        for (int j = 0; j < 3; j++)
            Z[i][j] = { sp[i * 3 + j], 0.0f };
#pragma unroll
    for (int i = 0; i < 3; i++)
        frft3(Z[i][0], Z[i][1], Z[i][2], c1a, c1b, c2a, c2b, scl);
#pragma unroll
    for (int j = 0; j < 3; j++)
        frft3(Z[0][j], Z[1][j], Z[2][j], c1a, c1b, c2a, c2b, scl);

    float pw0 = polarw[0];
    float pw1 = polarw[1];
    int co = id >> 6, ci = id & 63;
    float* gw = g_wK + co * 576 + ci * 9;
#pragma unroll
    for (int i = 0; i < 3; i++)
#pragma unroll
        for (int j = 0; j < 3; j++) {
            float re = Z[i][j].re, im = Z[i][j].im;
            float mag = sqrtf(re * re + im * im);
            float ang = atan2f(im, re);
            gw[i * 3 + j] = pw0 * mag + pw1 * (ang * (1.0f / PI_F));
        }
}

// ---------------- B-fragment build: g_wK -> g_BfragH (fp16) ----------------
// Step s = ch*9 + tap, chunk ch covers ci = ch*16 .. ch*16+15.
// b0 = {W[co][c0+2tig][tap], W[co][c0+2tig+1][tap]}  (x = even ci = k 2t)
// b1 = same with ci += 8.
__global__ void frfd_bfragH_kernel() {
    int s   = blockIdx.x;           // 0..35
    int tid = threadIdx.x;          // 256 = 8 nt * 32 lanes
    int nt   = tid >> 5;
    int lane = tid & 31;
    int gid  = lane >> 2;
    int tig  = lane & 3;
    int ch  = s / 9;
    int tap = s - ch * 9;
    int co  = nt * 8 + gid;
    int c0  = ch * 16;

    float w00 = g_wK[co * 576 + (c0 + 2 * tig)     * 9 + tap];
    float w01 = g_wK[co * 576 + (c0 + 2 * tig + 1) * 9 + tap];
    float w10 = g_wK[co * 576 + (c0 + 8 + 2 * tig)     * 9 + tap];
    float w11 = g_wK[co * 576 + (c0 + 8 + 2 * tig + 1) * 9 + tap];

    __half2 h0 = __floats2half2_rn(w00, w01);
    __half2 h1 = __floats2half2_rn(w10, w11);
    uint2 packed;
    packed.x = *reinterpret_cast<u32*>(&h0);
    packed.y = *reinterpret_cast<u32*>(&h1);
    g_BfragH[(s * 8 + nt) * 32 + lane] = packed;
}

// --------------------------------- conv mma ---------------------------------
__device__ __forceinline__ void mma16(float* c,
                                      u32 a0, u32 a1, u32 a2, u32 a3,
                                      u32 b0, u32 b1) {
    asm volatile(
        "mma.sync.aligned.m16n8k16.row.col.f32.f16.f16.f32 "
        "{%0,%1,%2,%3}, {%4,%5,%6,%7}, {%8,%9}, {%0,%1,%2,%3};"
        : "+f"(c[0]), "+f"(c[1]), "+f"(c[2]), "+f"(c[3])
        : "r"(a0), "r"(a1), "r"(a2), "r"(a3), "r"(b0), "r"(b1));
}

__global__ __launch_bounds__(128, 2)
void frfd_conv_mma(const float* __restrict__ x, float* __restrict__ out) {
    // double-buffered A: [buf][ci2(8)][row(10)][col(36, 34 used)] half2 words
    // ci2 = local ci pair index (covers 16 ci per chunk)
    __shared__ __align__(16) u32 sA[2][8 * 10 * 36];

    const int tid  = threadIdx.x;       // 128
    const int wz   = tid >> 5;          // warp 0..3 -> h row pair
    const int lane = tid & 31;
    const int gid  = lane >> 2;
    const int tig  = lane & 3;

    const int w0 = blockIdx.x * 32;
    const int h0 = blockIdx.y * 8;
    const int n  = blockIdx.z;

    // per-thread A word offsets for the 9 tap-steps:
    //   lo: ci2 = tig (k = 2tig, 2tig+1), hi: ci2 = tig + 4 (k = 2tig+8, +9)
    //   tig stride 360 words == 8 mod 32 -> conflict-free LDS
    u32 dApack[9];
#pragma unroll
    for (int kt = 0; kt < 9; ++kt) {
        int tapoff = (kt / 3) * 36 + (kt % 3);
        int lo = tig * 360 + tapoff;
        int hi = lo + 4 * 360;
        dApack[kt] = (u32)lo | ((u32)hi << 16);
    }

    // 4 m-tile spatial bases: (rh, wt)
    int mBase[2][2];
#pragma unroll
    for (int rh = 0; rh < 2; ++rh)
#pragma unroll
        for (int wt = 0; wt < 2; ++wt)
            mBase[rh][wt] = (2 * wz + rh) * 36 + wt * 16 + gid;

    float acc[2][2][8][4];
#pragma unroll
    for (int rh = 0; rh < 2; ++rh)
#pragma unroll
        for (int wt = 0; wt < 2; ++wt)
#pragma unroll
            for (int nt = 0; nt < 8; ++nt)
#pragma unroll
                for (int c = 0; c < 4; ++c) acc[rh][wt][nt][c] = 0.0f;

    const float* xb = x + (size_t)n * 64 * 50176;

    // ---- prologue: stage chunk 0 (ci 0..15 as 8 half2 planes) ----
    for (int idx = tid; idx < 2720; idx += 128) {
        int ci2 = idx / 340;
        int rem = idx - ci2 * 340;
        int r   = rem / 34;
        int c   = rem - r * 34;
        int gh = h0 - 1 + r;
        int gw = w0 - 1 + c;
        float v0 = 0.0f, v1 = 0.0f;
        if ((unsigned)gh < 224u && (unsigned)gw < 224u) {
            const float* p = xb + (size_t)(2 * ci2) * 50176 + gh * 224 + gw;
            v0 = __ldg(p);
            v1 = __ldg(p + 50176);
        }
        __half2 h = __floats2half2_rn(v0, v1);
        sA[0][ci2 * 360 + r * 36 + c] = *reinterpret_cast<u32*>(&h);
    }
    __syncthreads();

    for (int ch = 0; ch < 4; ++ch) {
        const u32* __restrict__ aBuf = sA[ch & 1];

        // ---- prefetch chunk ch+1 into registers (fly during mma) ----
        u32 vpre[22];
        if (ch < 3) {
            const float* xc = xb + (size_t)(ch + 1) * 16 * 50176;
#pragma unroll
            for (int k = 0; k < 22; ++k) {
                int idx = tid + k * 128;
                float v0 = 0.0f, v1 = 0.0f;
                if (idx < 2720) {
                    int ci2 = idx / 340;
                    int rem = idx - ci2 * 340;
                    int r   = rem / 34;
                    int c   = rem - r * 34;
                    int gh = h0 - 1 + r;
                    int gw = w0 - 1 + c;
                    if ((unsigned)gh < 224u && (unsigned)gw < 224u) {
                        const float* p = xc + (size_t)(2 * ci2) * 50176 + gh * 224 + gw;
                        v0 = __ldg(p);
                        v1 = __ldg(p + 50176);
                    }
                }
                __half2 h = __floats2half2_rn(v0, v1);
                vpre[k] = *reinterpret_cast<u32*>(&h);
            }
        }

        // ---- 9 tap-steps x (4 m-tiles x 8 n-tiles) k16 mma ----
        const uint2* bChunk = g_BfragH + (size_t)ch * 9 * 8 * 32 + lane;
#pragma unroll 3
        for (int kt = 0; kt < 9; ++kt) {
            u32 p = dApack[kt];
            const u32* aLo = aBuf + (p & 0xFFFFu);
            const u32* aHi = aBuf + (p >> 16);
            u32 a[2][2][4];
#pragma unroll
            for (int rh = 0; rh < 2; ++rh)
#pragma unroll
                for (int wt = 0; wt < 2; ++wt) {
                    int b = mBase[rh][wt];
                    a[rh][wt][0] = aLo[b];        // rows g,   k 2t..2t+1
                    a[rh][wt][1] = aLo[b + 8];    // rows g+8, k 2t..2t+1
                    a[rh][wt][2] = aHi[b];        // rows g,   k 2t+8..2t+9
                    a[rh][wt][3] = aHi[b + 8];    // rows g+8, k 2t+8..2t+9
                }
            const uint2* bp = bChunk + (size_t)kt * 256;
#pragma unroll
            for (int nt = 0; nt < 8; ++nt) {
                uint2 bb = __ldg(bp + nt * 32);
#pragma unroll
                for (int rh = 0; rh < 2; ++rh)
#pragma unroll
                    for (int wt = 0; wt < 2; ++wt)
                        mma16(acc[rh][wt][nt],
                              a[rh][wt][0], a[rh][wt][1],
                              a[rh][wt][2], a[rh][wt][3],
                              bb.x, bb.y);
            }
        }

        // ---- store prefetched chunk into the other buffer ----
        if (ch < 3) {
            u32* dst = sA[(ch + 1) & 1];
#pragma unroll
            for (int k = 0; k < 22; ++k) {
                int idx = tid + k * 128;
                if (idx < 2720) {
                    int ci2 = idx / 340;
                    int rem = idx - ci2 * 340;
                    int r   = rem / 34;
                    int c   = rem - r * 34;
                    dst[ci2 * 360 + r * 36 + c] = vpre[k];
                }
            }
        }
        __syncthreads();
    }

    // ---- epilogue: scatter stores (same m16n8 C layout as before) ----
    float* ob = out + (size_t)n * 64 * 50176;
#pragma unroll
    for (int nt = 0; nt < 8; ++nt) {
        int co = nt * 8 + tig * 2;
#pragma unroll
        for (int rh = 0; rh < 2; ++rh) {
            int h = h0 + 2 * wz + rh;
            float* p0 = ob + (size_t)co * 50176 + h * 224 + w0 + gid;
            float* p1 = p0 + 50176;
#pragma unroll
            for (int wt = 0; wt < 2; ++wt) {
                float* q0 = p0 + wt * 16;
                float* q1 = p1 + wt * 16;
                q0[0] = acc[rh][wt][nt][0];
                q1[0] = acc[rh][wt][nt][1];
                q0[8] = acc[rh][wt][nt][2];
                q1[8] = acc[rh][wt][nt][3];
            }
        }
    }
}

// --------------------------------- launcher ---------------------------------
extern "C" void kernel_launch(void* const* d_in, const int* in_sizes, int n_in,
                              void* d_out, int out_size) {
    int ix = 0, ispec = 1, ialpha = 2, ipw = 3;
    for (int i = 0; i < n_in; ++i) {
        int s = in_sizes[i];
        if (s == 16 * 64 * 224 * 224) ix = i;
        else if (s == 64 * 64 * 3 * 3) ispec = i;
        else if (s == 1) ialpha = i;
        else if (s == 2) ipw = i;
    }
    const float* x     = (const float*)d_in[ix];
    const float* spec  = (const float*)d_in[ispec];
    const float* alpha = (const float*)d_in[ialpha];
    const float* pw    = (const float*)d_in[ipw];
    float* out = (float*)d_out;

    frfd_wgen_kernel<<<16, 256>>>(spec, alpha, pw);
    frfd_bfragH_kernel<<<36, 256>>>();

    dim3 grid(7, 28, 16);
    frfd_conv_mma<<<grid, 128>>>(x, out);
}